// round 5
// baseline (speedup 1.0000x reference)
#include <cuda_runtime.h>

#define HID 128
#define NMAX 100000
#define EMAX 1600000
#define GMAX 64
#define SCAN_B 512

// ---- scratch (static device globals; no allocation) ----
// float4-typed => guaranteed 16B alignment for LDG/STG.128
__device__ float4 g_h2 [(size_t)NMAX * (HID / 4)];  // GEMM output (message source)
__device__ float4 g_acc[(size_t)NMAX * (HID / 4)];  // aggregated output per layer
__device__ float  g_dis[NMAX];                      // deg^{-1/2}
__device__ float  g_cnt[GMAX];                      // per-graph node counts
__device__ int    g_deg[NMAX];                      // in-degree (no self loop)
__device__ int    g_cur[NMAX];                      // fill cursor
__device__ int    g_rowptr[NMAX + 1];               // CSR row pointers (by dst)
__device__ int    g_csr[EMAX];                      // src ids grouped by dst
__device__ int    g_blksum[(NMAX + SCAN_B - 1) / SCAN_B];

__device__ __forceinline__ int clampi(int v, int hi) {
    return v < 0 ? 0 : (v > hi ? hi : v);
}

// ---------------------------------------------------------------------------
__global__ void k_init(float* __restrict__ out, int N, int out_elems) {
    int i = blockIdx.x * blockDim.x + threadIdx.x;
    if (i < N) { g_deg[i] = 0; g_cur[i] = 0; }
    if (i < GMAX) g_cnt[i] = 0.0f;
    if (i < out_elems) out[i] = 0.0f;
}

__global__ void k_count(const int* __restrict__ dst, int E, int N) {
    int e = blockIdx.x * blockDim.x + threadIdx.x;
    if (e < E) atomicAdd(&g_deg[clampi(dst[e], N - 1)], 1);
}

// --- exclusive scan of g_deg -> g_rowptr (3 stages) ---
__global__ void k_scan1(int N) {
    __shared__ int sm[SCAN_B];
    int t = threadIdx.x;
    int i = blockIdx.x * SCAN_B + t;
    int v = (i < N) ? g_deg[i] : 0;
    sm[t] = v;
    __syncthreads();
    #pragma unroll
    for (int off = 1; off < SCAN_B; off <<= 1) {
        int x = (t >= off) ? sm[t - off] : 0;
        __syncthreads();
        sm[t] += x;
        __syncthreads();
    }
    if (i < N) g_rowptr[i] = sm[t] - v;          // exclusive
    if (t == SCAN_B - 1) g_blksum[blockIdx.x] = sm[t];
}

__global__ void k_scan2(int nb) {
    if (threadIdx.x == 0) {
        int run = 0;
        for (int i = 0; i < nb; i++) { int v = g_blksum[i]; g_blksum[i] = run; run += v; }
    }
}

__global__ void k_scan3(int N, int E) {
    int i = blockIdx.x * blockDim.x + threadIdx.x;
    if (i < N) g_rowptr[i] += g_blksum[i / SCAN_B];
    if (i == 0) g_rowptr[N] = E;
}

__global__ void k_fill(const int* __restrict__ src,
                       const int* __restrict__ dst, int E, int N) {
    int e = blockIdx.x * blockDim.x + threadIdx.x;
    if (e >= E) return;
    int d = clampi(dst[e], N - 1);
    int pos = atomicAdd(&g_cur[d], 1);
    int idx = clampi(g_rowptr[d] + pos, EMAX - 1);
    g_csr[idx] = clampi(src[e], N - 1);
}

__global__ void k_rsqrt(int N) {
    int i = blockIdx.x * blockDim.x + threadIdx.x;
    if (i < N) g_dis[i] = rsqrtf((float)(g_deg[i] + 1));   // +1 self loop
}

// ---------------------------------------------------------------------------
// GEMM: h2 = f(in) @ W
// f(in) = in (layer 0) ; relu(in + bias_prev) (layers > 0, in = g_acc)
// ---------------------------------------------------------------------------
__global__ void __launch_bounds__(256) k_gemm(
    const float* __restrict__ xin,
    const float* __restrict__ W,
    const float* __restrict__ bias,
    int use_acc,
    int N)
{
    extern __shared__ float sm[];
    float* xs = sm;                 // [128][128]
    float* ws = sm + 128 * HID;     // [128][128]

    const int tid  = threadIdx.x;
    const int base = blockIdx.x * 128;

    {
        const float4* Wv  = (const float4*)W;
        float4*       wsv = (float4*)ws;
        #pragma unroll
        for (int i = 0; i < 16; i++)
            wsv[i * 256 + tid] = Wv[i * 256 + tid];
    }
    {
        float4* xsv = (float4*)xs;
        #pragma unroll
        for (int i = 0; i < 16; i++) {
            int o = i * 256 + tid;
            int r = o >> 5;
            int q = o & 31;
            float4 v = make_float4(0.f, 0.f, 0.f, 0.f);
            if (base + r < N) {
                if (use_acc) {
                    v = g_acc[(size_t)(base + r) * 32 + q];
                    int k4 = q * 4;
                    v.x = fmaxf(v.x + bias[k4 + 0], 0.0f);
                    v.y = fmaxf(v.y + bias[k4 + 1], 0.0f);
                    v.z = fmaxf(v.z + bias[k4 + 2], 0.0f);
                    v.w = fmaxf(v.w + bias[k4 + 3], 0.0f);
                } else {
                    v = ((const float4*)(xin + (size_t)(base + r) * HID))[q];
                }
            }
            xsv[o] = v;
        }
    }
    __syncthreads();

    const int tx = tid & 15;
    const int ty = tid >> 4;
    const int r0 = ty * 8;
    const int c0 = tx * 8;

    float accv[8][8];
    #pragma unroll
    for (int i = 0; i < 8; i++)
        #pragma unroll
        for (int j = 0; j < 8; j++) accv[i][j] = 0.0f;

    #pragma unroll 8
    for (int k = 0; k < HID; k++) {
        float xv[8];
        #pragma unroll
        for (int i = 0; i < 8; i++) xv[i] = xs[(r0 + i) * HID + k];
        float4 w0 = *(const float4*)(ws + k * HID + c0);
        float4 w1 = *(const float4*)(ws + k * HID + c0 + 4);
        float wv[8] = {w0.x, w0.y, w0.z, w0.w, w1.x, w1.y, w1.z, w1.w};
        #pragma unroll
        for (int i = 0; i < 8; i++)
            #pragma unroll
            for (int j = 0; j < 8; j++)
                accv[i][j] += xv[i] * wv[j];
    }

    #pragma unroll
    for (int i = 0; i < 8; i++) {
        int r = base + r0 + i;
        if (r < N) {
            g_h2[(size_t)r * 32 + (c0 >> 2)] =
                make_float4(accv[i][0], accv[i][1], accv[i][2], accv[i][3]);
            g_h2[(size_t)r * 32 + (c0 >> 2) + 1] =
                make_float4(accv[i][4], accv[i][5], accv[i][6], accv[i][7]);
        }
    }
}

// ---------------------------------------------------------------------------
// gather-aggregate: one warp per dst node. 32 lanes x float4 = 128 features.
// acc[n] = h2[n]*dis[n]^2 + sum_{s in in(n)} h2[s]*dis[s]*dis[n]
// ---------------------------------------------------------------------------
__global__ void __launch_bounds__(256) k_aggr(int N) {
    int w    = (int)((blockIdx.x * (unsigned)blockDim.x + threadIdx.x) >> 5);
    int lane = threadIdx.x & 31;
    if (w >= N) return;

    int beg = clampi(g_rowptr[w],     EMAX);
    int end = clampi(g_rowptr[w + 1], EMAX);
    float dn = g_dis[w];

    float4 h = g_h2[(size_t)w * 32 + lane];
    float sn = dn * dn;
    float4 a = make_float4(h.x * sn, h.y * sn, h.z * sn, h.w * sn);

    for (int e = beg; e < end; e++) {
        int s = g_csr[e];
        float nm = dn * g_dis[s];
        float4 v = g_h2[(size_t)s * 32 + lane];
        a.x += v.x * nm; a.y += v.y * nm; a.z += v.z * nm; a.w += v.w * nm;
    }
    g_acc[(size_t)w * 32 + lane] = a;
}

// ---------------------------------------------------------------------------
// pooling (batch sorted): running sums, flush on graph-id change
// ---------------------------------------------------------------------------
#define POOL_CHUNK 256
__global__ void __launch_bounds__(HID) k_pool(
    const int* __restrict__ batch,
    const float* __restrict__ bias,
    float* __restrict__ out,
    int N)
{
    int j     = threadIdx.x;
    int start = blockIdx.x * POOL_CHUNK;
    if (start >= N) return;
    int end = start + POOL_CHUNK;
    if (end > N) end = N;

    const float* accf = (const float*)g_acc;

    float b   = bias[j];
    int   cur = clampi(batch[start], GMAX - 1);
    float sum = 0.0f;
    float cnt = 0.0f;

    for (int r = start; r < end; r++) {
        int g = clampi(batch[r], GMAX - 1);
        if (g != cur) {
            atomicAdd(out + (size_t)cur * HID + j, sum);
            if (j == 0) atomicAdd(&g_cnt[cur], cnt);
            sum = 0.0f; cnt = 0.0f; cur = g;
        }
        sum += fmaxf(accf[(size_t)r * HID + j] + b, 0.0f);
        cnt += 1.0f;
    }
    atomicAdd(out + (size_t)cur * HID + j, sum);
    if (j == 0) atomicAdd(&g_cnt[cur], cnt);
}

__global__ void k_div(float* __restrict__ out, int out_elems) {
    int i = blockIdx.x * blockDim.x + threadIdx.x;
    if (i < out_elems) out[i] /= fmaxf(g_cnt[i >> 7], 1.0f);
}

// ---------------------------------------------------------------------------
extern "C" void kernel_launch(void* const* d_in, const int* in_sizes, int n_in,
                              void* d_out, int out_size) {
    const float* x     = (const float*)d_in[0];
    const int*   ei    = (const int*)d_in[1];     // int32 (JAX x64 disabled)
    const int*   batch = (const int*)d_in[2];     // int32
    const float* Ws    = (const float*)d_in[3];
    const float* bs    = (const float*)d_in[4];
    float*       out   = (float*)d_out;

    const int N = in_sizes[0] / HID;
    const int E = in_sizes[1] / 2;
    const int* srcp = ei;
    const int* dstp = ei + E;

    const size_t smem = 2 * 128 * HID * sizeof(float);   // 128 KB
    cudaFuncSetAttribute(k_gemm, cudaFuncAttributeMaxDynamicSharedMemorySize,
                         (int)smem);

    const int nb_scan = (N + SCAN_B - 1) / SCAN_B;

    k_init  <<<(N + 255) / 256, 256>>>(out, N, out_size);
    k_count <<<(E + 255) / 256, 256>>>(dstp, E, N);
    k_scan1 <<<nb_scan, SCAN_B>>>(N);
    k_scan2 <<<1, 32>>>(nb_scan);
    k_scan3 <<<(N + 255) / 256, 256>>>(N, E);
    k_fill  <<<(E + 255) / 256, 256>>>(srcp, dstp, E, N);
    k_rsqrt <<<(N + 255) / 256, 256>>>(N);

    const int gemm_blocks = (N + 127) / 128;
    const int aggr_blocks = (int)(((long long)N * 32 + 255) / 256);

    for (int l = 0; l < 3; l++) {
        const float* bias_prev = (l == 0) ? bs : (bs + (size_t)(l - 1) * HID);
        k_gemm<<<gemm_blocks, 256, smem>>>(
            x, Ws + (size_t)l * HID * HID, bias_prev, l > 0 ? 1 : 0, N);
        k_aggr<<<aggr_blocks, 256>>>(N);
    }

    k_pool<<<(N + POOL_CHUNK - 1) / POOL_CHUNK, HID>>>(batch, bs + 2 * HID, out, N);
    k_div <<<(out_size + 255) / 256, 256>>>(out, out_size);
}